// round 1
// baseline (speedup 1.0000x reference)
#include <cuda_runtime.h>
#include <math.h>

#define B_  4
#define S_  1024
#define D_  768
#define H_  384
#define NROW (B_*S_)            // 4096
#define BOND_ 3.8f
#define LR_ 0.01f
#define BETA1_ 0.9f
#define BETA2_ 0.999f
#define ADAM_EPS_ 1e-8f
#define NSTEPS_ 50

// ----- device scratch (no allocations allowed) -----
__device__ float g_h[NROW * H_];          // hidden after ReLU (6 MB)
__device__ float g_delta[NROW * 3];
__device__ float g_xA[NROW * 3];
__device__ float g_xB[NROW * 3];
__device__ float g_m[NROW * 3];
__device__ float g_v[NROW * 3];
__device__ float g_cms[(size_t)B_ * S_ * S_];   // symmetrized + prescaled contact map (16 MB)

// =====================================================================
// K1a: C = ReLU(A[4096,768] @ W1[768,384] + b1) -> g_h
// BM=128, BN=64, BK=16, 256 threads, 8x4 per thread
// =====================================================================
#define BM 128
#define BN 64
#define BK 16

__global__ __launch_bounds__(256) void gemm_relu_kernel(
    const float* __restrict__ A, const float* __restrict__ W1,
    const float* __restrict__ b1)
{
    __shared__ float As[BK][BM];
    __shared__ float Bs[BK][BN];

    const int tid = threadIdx.x;
    const int tx = tid & 15;      // n-dir (16 x 4 = 64)
    const int ty = tid >> 4;      // m-dir (16 x 8 = 128)
    const int m0 = blockIdx.y * BM;
    const int n0 = blockIdx.x * BN;

    float acc[8][4];
#pragma unroll
    for (int i = 0; i < 8; i++)
#pragma unroll
        for (int j = 0; j < 4; j++) acc[i][j] = 0.f;

    for (int k0 = 0; k0 < D_; k0 += BK) {
        // A tile: 128 rows x 16 cols = 512 float4, 2 per thread (store transposed)
#pragma unroll
        for (int l = 0; l < 2; l++) {
            int idx = tid + l * 256;
            int row = idx >> 2;          // 0..127
            int c4  = idx & 3;           // 0..3
            float4 a = *(const float4*)(A + (size_t)(m0 + row) * D_ + k0 + c4 * 4);
            As[c4 * 4 + 0][row] = a.x;
            As[c4 * 4 + 1][row] = a.y;
            As[c4 * 4 + 2][row] = a.z;
            As[c4 * 4 + 3][row] = a.w;
        }
        // B tile: 16 rows x 64 cols = 256 float4, 1 per thread
        {
            int row = tid >> 4;          // 0..15
            int c4  = tid & 15;          // 0..15
            float4 bvec = *(const float4*)(W1 + (size_t)(k0 + row) * H_ + n0 + c4 * 4);
            *(float4*)&Bs[row][c4 * 4] = bvec;
        }
        __syncthreads();

#pragma unroll
        for (int k = 0; k < BK; k++) {
            float a[8], b[4];
            *(float4*)&a[0] = *(const float4*)&As[k][ty * 8];
            *(float4*)&a[4] = *(const float4*)&As[k][ty * 8 + 4];
            *(float4*)&b[0] = *(const float4*)&Bs[k][tx * 4];
#pragma unroll
            for (int i = 0; i < 8; i++)
#pragma unroll
                for (int j = 0; j < 4; j++)
                    acc[i][j] = fmaf(a[i], b[j], acc[i][j]);
        }
        __syncthreads();
    }

    float4 bias = *(const float4*)(b1 + n0 + tx * 4);
    float bv[4] = {bias.x, bias.y, bias.z, bias.w};
#pragma unroll
    for (int i = 0; i < 8; i++) {
        float4 o;
        o.x = fmaxf(acc[i][0] + bv[0], 0.f);
        o.y = fmaxf(acc[i][1] + bv[1], 0.f);
        o.z = fmaxf(acc[i][2] + bv[2], 0.f);
        o.w = fmaxf(acc[i][3] + bv[3], 0.f);
        *(float4*)(g_h + (size_t)(m0 + ty * 8 + i) * H_ + n0 + tx * 4) = o;
    }
}

// =====================================================================
// K1b: per-row phi/psi = h @ W2[:,0:2] + b2, then delta vector
// one block (128 threads) per row
// =====================================================================
__global__ __launch_bounds__(128) void angles_delta_kernel(
    const float* __restrict__ W2, const float* __restrict__ b2)
{
    const int row = blockIdx.x;
    const int tid = threadIdx.x;
    const float* h = g_h + (size_t)row * H_;

    float a0 = 0.f, a1 = 0.f;
#pragma unroll
    for (int j = tid; j < H_; j += 128) {
        float hv = h[j];
        a0 = fmaf(hv, W2[j * 3 + 0], a0);
        a1 = fmaf(hv, W2[j * 3 + 1], a1);
    }
#pragma unroll
    for (int off = 16; off; off >>= 1) {
        a0 += __shfl_down_sync(0xffffffffu, a0, off);
        a1 += __shfl_down_sync(0xffffffffu, a1, off);
    }
    __shared__ float s0[4], s1[4];
    int w = tid >> 5, lane = tid & 31;
    if (lane == 0) { s0[w] = a0; s1[w] = a1; }
    __syncthreads();
    if (tid == 0) {
        float phi = s0[0] + s0[1] + s0[2] + s0[3] + b2[0];
        float psi = s1[0] + s1[1] + s1[2] + s1[3] + b2[1];
        float dx, dy, dz;
        if ((row & (S_ - 1)) == 0) {
            dx = dy = dz = 0.f;
        } else {
            float sp, cp, ss, cs;
            sincosf(phi, &sp, &cp);
            sincosf(psi, &ss, &cs);
            dx = BOND_ * cp * cs;
            dy = BOND_ * sp * cs;
            dz = BOND_ * ss;
        }
        g_delta[row * 3 + 0] = dx;
        g_delta[row * 3 + 1] = dy;
        g_delta[row * 3 + 2] = dz;
    }
}

// =====================================================================
// K2: inclusive cumsum over sequence per (batch, dim) -> g_xA
// one block of 1024 threads per (b, dim): 12 blocks
// =====================================================================
__global__ __launch_bounds__(1024) void cumsum_kernel()
{
    const int b   = blockIdx.x / 3;
    const int dim = blockIdx.x % 3;
    const int s   = threadIdx.x;

    float v = g_delta[((b * S_) + s) * 3 + dim];
    int lane = s & 31, w = s >> 5;
#pragma unroll
    for (int off = 1; off < 32; off <<= 1) {
        float n = __shfl_up_sync(0xffffffffu, v, off);
        if (lane >= off) v += n;
    }
    __shared__ float wsum[32];
    if (lane == 31) wsum[w] = v;
    __syncthreads();
    if (w == 0) {
        float t = wsum[lane];
#pragma unroll
        for (int off = 1; off < 32; off <<= 1) {
            float n = __shfl_up_sync(0xffffffffu, t, off);
            if (lane >= off) t += n;
        }
        wsum[lane] = t;
    }
    __syncthreads();
    float excl = (w == 0) ? 0.f : wsum[w - 1];
    g_xA[((b * S_) + s) * 3 + dim] = v + excl;
}

// =====================================================================
// K0: cm_sym[b,i,j] = (cm[b,i,j] + cm[b,j,i]) / (B*S*S)   (tiled transpose-add)
// =====================================================================
__global__ void cmsym_kernel(const float* __restrict__ cm)
{
    __shared__ float ts[32][33];
    const int b  = blockIdx.z;
    const int i0 = blockIdx.y * 32;
    const int j0 = blockIdx.x * 32;
    const float* cb = cm + (size_t)b * S_ * S_;
    float* ob = g_cms + (size_t)b * S_ * S_;
    const int tx = threadIdx.x, ty = threadIdx.y;   // 32 x 8
    const float invN = 1.0f / (float)((size_t)B_ * S_ * S_);

#pragma unroll
    for (int r = ty; r < 32; r += 8)
        ts[r][tx] = cb[(size_t)(j0 + r) * S_ + i0 + tx];
    __syncthreads();
#pragma unroll
    for (int r = ty; r < 32; r += 8)
        ob[(size_t)(i0 + r) * S_ + j0 + tx] =
            (cb[(size_t)(i0 + r) * S_ + j0 + tx] + ts[tx][r]) * invN;
}

// =====================================================================
// zero Adam moments
// =====================================================================
__global__ void zero_mv_kernel()
{
    int i = blockIdx.x * 256 + threadIdx.x;
    if (i < NROW * 3) { g_m[i] = 0.f; g_v[i] = 0.f; }
}

// =====================================================================
// K3: one Adam step: gradient of contact loss + parameter update
// 512 blocks x 256 threads; warp-per-row (8 rows/block)
// =====================================================================
__global__ __launch_bounds__(256) void adam_step_kernel(
    const float* __restrict__ xin, float* __restrict__ xout,
    float c1, float c2)
{
    __shared__ float xs[S_], ys[S_], zs[S_];
    const int tid  = threadIdx.x;
    const int bidx = blockIdx.x;        // 0..511
    const int b    = bidx >> 7;         // /128
    const int rb   = (bidx & 127) * 8;

    const float* xb = xin + (size_t)b * S_ * 3;
    for (int s = tid; s < S_; s += 256) {
        xs[s] = xb[s * 3 + 0];
        ys[s] = xb[s * 3 + 1];
        zs[s] = xb[s * 3 + 2];
    }
    __syncthreads();

    const int w = tid >> 5, lane = tid & 31;
    const int si = rb + w;
    const float xi = xs[si], yi = ys[si], zi = zs[si];
    const float* crow = g_cms + ((size_t)b * S_ + si) * S_;

    float gx = 0.f, gy = 0.f, gz = 0.f;
#pragma unroll 4
    for (int j = lane; j < S_; j += 32) {
        float c  = __ldg(crow + j);
        float dx = xi - xs[j];
        float dy = yi - ys[j];
        float dz = zi - zs[j];
        float d2 = fmaf(dx, dx, 1e-12f);
        d2 = fmaf(dy, dy, d2);
        d2 = fmaf(dz, dz, d2);
        float inv = rsqrtf(d2);
        float wgt = (d2 > 64.0f ? c : -c) * inv;   // sign(d-8) * cm_sym / d
        gx = fmaf(wgt, dx, gx);
        gy = fmaf(wgt, dy, gy);
        gz = fmaf(wgt, dz, gz);
    }
#pragma unroll
    for (int off = 16; off; off >>= 1) {
        gx += __shfl_down_sync(0xffffffffu, gx, off);
        gy += __shfl_down_sync(0xffffffffu, gy, off);
        gz += __shfl_down_sync(0xffffffffu, gz, off);
    }

    if (lane == 0) {
        size_t gi = ((size_t)b * S_ + si) * 3;
        float xo[3] = {xi, yi, zi};
        float g[3]  = {gx, gy, gz};
#pragma unroll
        for (int d = 0; d < 3; d++) {
            float m = g_m[gi + d] * BETA1_ + (1.f - BETA1_) * g[d];
            float v = g_v[gi + d] * BETA2_ + (1.f - BETA2_) * g[d] * g[d];
            g_m[gi + d] = m;
            g_v[gi + d] = v;
            float mh = m * c1;
            float vh = v * c2;
            xout[gi + d] = xo[d] - LR_ * mh / (sqrtf(vh) + ADAM_EPS_);
        }
    }
}

// =====================================================================
// host launcher (graph-capturable: kernel launches only)
// =====================================================================
extern "C" void kernel_launch(void* const* d_in, const int* in_sizes, int n_in,
                              void* d_out, int out_size)
{
    const float* bf  = (const float*)d_in[0];   // backbone_features [4,1024,768]
    const float* cm  = (const float*)d_in[2];   // contact_map [4,1024,1024]
    const float* Wb1 = (const float*)d_in[3];
    const float* bb1 = (const float*)d_in[4];
    const float* Wb2 = (const float*)d_in[5];
    const float* bb2 = (const float*)d_in[6];
    float* out = (float*)d_out;

    gemm_relu_kernel<<<dim3(H_ / BN, NROW / BM), 256>>>(bf, Wb1, bb1);
    angles_delta_kernel<<<NROW, 128>>>(Wb2, bb2);
    cmsym_kernel<<<dim3(S_ / 32, S_ / 32, B_), dim3(32, 8)>>>(cm);
    cumsum_kernel<<<B_ * 3, S_>>>();
    zero_mv_kernel<<<(NROW * 3 + 255) / 256, 256>>>();

    float *xA = nullptr, *xB = nullptr;
    cudaGetSymbolAddress((void**)&xA, g_xA);
    cudaGetSymbolAddress((void**)&xB, g_xB);

    float b1t = 1.f, b2t = 1.f;
    for (int t = 1; t <= NSTEPS_; t++) {
        b1t *= BETA1_;
        b2t *= BETA2_;
        float c1 = 1.f / (1.f - b1t);
        float c2 = 1.f / (1.f - b2t);
        const float* xin = (t & 1) ? xA : xB;
        float* xout = (t == NSTEPS_) ? out : ((t & 1) ? xB : xA);
        adam_step_kernel<<<512, 256>>>(xin, xout, c1, c2);
    }
}

// round 2
// speedup vs baseline: 1.3075x; 1.3075x over previous
#include <cuda_runtime.h>
#include <math.h>

#define B_  4
#define S_  1024
#define D_  768
#define H_  384
#define NROW (B_*S_)            // 4096
#define BOND_ 3.8f
#define LR_ 0.01f
#define BETA1_ 0.9f
#define BETA2_ 0.999f
#define ADAM_EPS_ 1e-8f
#define NSTEPS_ 50

// ----- device scratch (no allocations allowed) -----
__device__ float g_h[NROW * H_];               // hidden after ReLU (6 MB)
__device__ float g_delta[NROW * 3];
__device__ float4 g_xA4[NROW];                 // ping-pong position buffers (float4)
__device__ float4 g_xB4[NROW];
__device__ float g_cms[(size_t)B_ * S_ * S_];  // symmetrized + prescaled contact map (16 MB)
__device__ unsigned g_cnt[B_];                 // per-batch barrier counters (zero-init)
__device__ unsigned g_ph[B_];                  // per-batch barrier phases (monotonic)

// =====================================================================
// K1a: C = ReLU(A[4096,768] @ W1[768,384] + b1) -> g_h
// BM=BN=64, BK=16, 256 threads, 4x4 per thread; 384 blocks (balanced)
// =====================================================================
__global__ __launch_bounds__(256) void gemm_relu_kernel(
    const float* __restrict__ A, const float* __restrict__ W1,
    const float* __restrict__ b1)
{
    __shared__ float As[16][64];
    __shared__ float Bs[16][64];

    const int tid = threadIdx.x;
    const int tx = tid & 15;      // n-dir (16 x 4 = 64)
    const int ty = tid >> 4;      // m-dir (16 x 4 = 64)
    const int m0 = blockIdx.y * 64;
    const int n0 = blockIdx.x * 64;

    float acc[4][4];
#pragma unroll
    for (int i = 0; i < 4; i++)
#pragma unroll
        for (int j = 0; j < 4; j++) acc[i][j] = 0.f;

    for (int k0 = 0; k0 < D_; k0 += 16) {
        // A tile: 64 rows x 16 cols = 256 float4, 1 per thread (store transposed)
        {
            int row = tid >> 2;          // 0..63
            int c4  = tid & 3;           // 0..3
            float4 a = *(const float4*)(A + (size_t)(m0 + row) * D_ + k0 + c4 * 4);
            As[c4 * 4 + 0][row] = a.x;
            As[c4 * 4 + 1][row] = a.y;
            As[c4 * 4 + 2][row] = a.z;
            As[c4 * 4 + 3][row] = a.w;
        }
        // B tile: 16 rows x 64 cols = 256 float4, 1 per thread
        {
            int row = tid >> 4;          // 0..15
            int c4  = tid & 15;          // 0..15
            *(float4*)&Bs[row][c4 * 4] =
                *(const float4*)(W1 + (size_t)(k0 + row) * H_ + n0 + c4 * 4);
        }
        __syncthreads();

#pragma unroll
        for (int k = 0; k < 16; k++) {
            float a[4], b[4];
            *(float4*)&a[0] = *(const float4*)&As[k][ty * 4];
            *(float4*)&b[0] = *(const float4*)&Bs[k][tx * 4];
#pragma unroll
            for (int i = 0; i < 4; i++)
#pragma unroll
                for (int j = 0; j < 4; j++)
                    acc[i][j] = fmaf(a[i], b[j], acc[i][j]);
        }
        __syncthreads();
    }

    float4 bias = *(const float4*)(b1 + n0 + tx * 4);
    float bv[4] = {bias.x, bias.y, bias.z, bias.w};
#pragma unroll
    for (int i = 0; i < 4; i++) {
        float4 o;
        o.x = fmaxf(acc[i][0] + bv[0], 0.f);
        o.y = fmaxf(acc[i][1] + bv[1], 0.f);
        o.z = fmaxf(acc[i][2] + bv[2], 0.f);
        o.w = fmaxf(acc[i][3] + bv[3], 0.f);
        *(float4*)(g_h + (size_t)(m0 + ty * 4 + i) * H_ + n0 + tx * 4) = o;
    }
}

// =====================================================================
// K1b: per-row phi/psi = h @ W2[:,0:2] + b2, then delta vector
// =====================================================================
__global__ __launch_bounds__(128) void angles_delta_kernel(
    const float* __restrict__ W2, const float* __restrict__ b2)
{
    const int row = blockIdx.x;
    const int tid = threadIdx.x;
    const float* h = g_h + (size_t)row * H_;

    float a0 = 0.f, a1 = 0.f;
#pragma unroll
    for (int j = tid; j < H_; j += 128) {
        float hv = h[j];
        a0 = fmaf(hv, W2[j * 3 + 0], a0);
        a1 = fmaf(hv, W2[j * 3 + 1], a1);
    }
#pragma unroll
    for (int off = 16; off; off >>= 1) {
        a0 += __shfl_down_sync(0xffffffffu, a0, off);
        a1 += __shfl_down_sync(0xffffffffu, a1, off);
    }
    __shared__ float s0[4], s1[4];
    int w = tid >> 5, lane = tid & 31;
    if (lane == 0) { s0[w] = a0; s1[w] = a1; }
    __syncthreads();
    if (tid == 0) {
        float phi = s0[0] + s0[1] + s0[2] + s0[3] + b2[0];
        float psi = s1[0] + s1[1] + s1[2] + s1[3] + b2[1];
        float dx, dy, dz;
        if ((row & (S_ - 1)) == 0) {
            dx = dy = dz = 0.f;
        } else {
            float sp, cp, ss, cs;
            sincosf(phi, &sp, &cp);
            sincosf(psi, &ss, &cs);
            dx = BOND_ * cp * cs;
            dy = BOND_ * sp * cs;
            dz = BOND_ * ss;
        }
        g_delta[row * 3 + 0] = dx;
        g_delta[row * 3 + 1] = dy;
        g_delta[row * 3 + 2] = dz;
    }
}

// =====================================================================
// K2: inclusive cumsum over sequence per (batch, dim) -> g_xA4 (float4 layout)
// =====================================================================
__global__ __launch_bounds__(1024) void cumsum_kernel()
{
    const int b   = blockIdx.x / 3;
    const int dim = blockIdx.x % 3;
    const int s   = threadIdx.x;

    float v = g_delta[((b * S_) + s) * 3 + dim];
    int lane = s & 31, w = s >> 5;
#pragma unroll
    for (int off = 1; off < 32; off <<= 1) {
        float n = __shfl_up_sync(0xffffffffu, v, off);
        if (lane >= off) v += n;
    }
    __shared__ float wsum[32];
    if (lane == 31) wsum[w] = v;
    __syncthreads();
    if (w == 0) {
        float t = wsum[lane];
#pragma unroll
        for (int off = 1; off < 32; off <<= 1) {
            float n = __shfl_up_sync(0xffffffffu, t, off);
            if (lane >= off) t += n;
        }
        wsum[lane] = t;
    }
    __syncthreads();
    float excl = (w == 0) ? 0.f : wsum[w - 1];
    ((float*)g_xA4)[((b * S_) + s) * 4 + dim] = v + excl;
}

// =====================================================================
// K0: cm_sym[b,i,j] = (cm[b,i,j] + cm[b,j,i]) / (B*S*S)
// =====================================================================
__global__ void cmsym_kernel(const float* __restrict__ cm)
{
    __shared__ float ts[32][33];
    const int b  = blockIdx.z;
    const int i0 = blockIdx.y * 32;
    const int j0 = blockIdx.x * 32;
    const float* cb = cm + (size_t)b * S_ * S_;
    float* ob = g_cms + (size_t)b * S_ * S_;
    const int tx = threadIdx.x, ty = threadIdx.y;   // 32 x 8
    const float invN = 1.0f / (float)((size_t)B_ * S_ * S_);

#pragma unroll
    for (int r = ty; r < 32; r += 8)
        ts[r][tx] = cb[(size_t)(j0 + r) * S_ + i0 + tx];
    __syncthreads();
#pragma unroll
    for (int r = ty; r < 32; r += 8)
        ob[(size_t)(i0 + r) * S_ + j0 + tx] =
            (cb[(size_t)(i0 + r) * S_ + j0 + tx] + ts[tx][r]) * invN;
}

// =====================================================================
// K3: persistent kernel — all 50 Adam steps in one launch.
// 512 blocks x 128 threads (4 warps). Block owns 8 rows (2 per warp).
// cm rows cached in smem across all steps; m/v in registers.
// Per-batch software grid barrier (128 blocks per batch).
// =====================================================================
__global__ __launch_bounds__(128, 4) void refine_kernel(float* __restrict__ out)
{
    __shared__ float4 pos[S_];          // 16 KB
    __shared__ float cmrow[8][S_];      // 32 KB  -> total 48 KB

    const int tid  = threadIdx.x;
    const int w    = tid >> 5;
    const int lane = tid & 31;
    const int b    = blockIdx.x >> 7;          // batch 0..3
    const int rb   = (blockIdx.x & 127) << 3;  // row base within batch
    const int r0   = rb + w * 2;               // this warp's rows: r0, r0+1

    // cache this warp's 2 contact-map rows in smem (once, reused 50 steps)
    {
        const float4* src0 = (const float4*)(g_cms + ((size_t)b * S_ + r0) * S_);
        const float4* src1 = (const float4*)(g_cms + ((size_t)b * S_ + r0 + 1) * S_);
        float4* d0 = (float4*)cmrow[w * 2];
        float4* d1 = (float4*)cmrow[w * 2 + 1];
        for (int k = lane; k < S_ / 4; k += 32) { d0[k] = src0[k]; d1[k] = src1[k]; }
    }

    unsigned ph0 = 0;
    if (tid == 0) ph0 = *(volatile unsigned*)&g_ph[b];

    float m[2][3] = {{0,0,0},{0,0,0}};
    float v[2][3] = {{0,0,0},{0,0,0}};
    float b1t = 1.f, b2t = 1.f;

    for (int t = 1; t <= NSTEPS_; t++) {
        const float4* xin = (t & 1) ? g_xA4 : g_xB4;
        float4* xout      = (t & 1) ? g_xB4 : g_xA4;

        // reload positions (updated by all blocks of this batch). .cg: bypass
        // stale L1 (x buffers are cross-SM mutable).
        const float4* xb = xin + b * S_;
        for (int s = tid; s < S_; s += 128) pos[s] = __ldcg(xb + s);
        __syncthreads();

        const float4 p0 = pos[r0];
        const float4 p1 = pos[r0 + 1];
        float g0x = 0.f, g0y = 0.f, g0z = 0.f;
        float g1x = 0.f, g1y = 0.f, g1z = 0.f;
        const float* c0 = cmrow[w * 2];
        const float* c1 = cmrow[w * 2 + 1];

#pragma unroll 2
        for (int it = 0; it < 8; it++) {
            const int j0 = it * 128 + lane * 4;
            float4 cA = *(const float4*)(c0 + j0);
            float4 cB = *(const float4*)(c1 + j0);
            float ca[4] = {cA.x, cA.y, cA.z, cA.w};
            float cb[4] = {cB.x, cB.y, cB.z, cB.w};
#pragma unroll
            for (int k = 0; k < 4; k++) {
                float4 pj = pos[j0 + k];
                // row 0
                float dx = p0.x - pj.x, dy = p0.y - pj.y, dz = p0.z - pj.z;
                float d2 = fmaf(dx, dx, 1e-12f);
                d2 = fmaf(dy, dy, d2);
                d2 = fmaf(dz, dz, d2);
                float wgt = (d2 > 64.f ? ca[k] : -ca[k]) * rsqrtf(d2);
                g0x = fmaf(wgt, dx, g0x);
                g0y = fmaf(wgt, dy, g0y);
                g0z = fmaf(wgt, dz, g0z);
                // row 1
                dx = p1.x - pj.x; dy = p1.y - pj.y; dz = p1.z - pj.z;
                d2 = fmaf(dx, dx, 1e-12f);
                d2 = fmaf(dy, dy, d2);
                d2 = fmaf(dz, dz, d2);
                wgt = (d2 > 64.f ? cb[k] : -cb[k]) * rsqrtf(d2);
                g1x = fmaf(wgt, dx, g1x);
                g1y = fmaf(wgt, dy, g1y);
                g1z = fmaf(wgt, dz, g1z);
            }
        }

#pragma unroll
        for (int off = 16; off; off >>= 1) {
            g0x += __shfl_down_sync(0xffffffffu, g0x, off);
            g0y += __shfl_down_sync(0xffffffffu, g0y, off);
            g0z += __shfl_down_sync(0xffffffffu, g0z, off);
            g1x += __shfl_down_sync(0xffffffffu, g1x, off);
            g1y += __shfl_down_sync(0xffffffffu, g1y, off);
            g1z += __shfl_down_sync(0xffffffffu, g1z, off);
        }

        b1t *= BETA1_;
        b2t *= BETA2_;

        if (lane == 0) {
            const float c1f = 1.f / (1.f - b1t);
            const float c2f = 1.f / (1.f - b2t);
            float gr[2][3] = {{g0x, g0y, g0z}, {g1x, g1y, g1z}};
            float px[2][3] = {{p0.x, p0.y, p0.z}, {p1.x, p1.y, p1.z}};
#pragma unroll
            for (int r = 0; r < 2; r++) {
                float nv[3];
#pragma unroll
                for (int d = 0; d < 3; d++) {
                    m[r][d] = BETA1_ * m[r][d] + (1.f - BETA1_) * gr[r][d];
                    v[r][d] = BETA2_ * v[r][d] + (1.f - BETA2_) * gr[r][d] * gr[r][d];
                    nv[d] = px[r][d] - LR_ * (m[r][d] * c1f) / (sqrtf(v[r][d] * c2f) + ADAM_EPS_);
                }
                if (t == NSTEPS_) {
                    size_t o = ((size_t)b * S_ + r0 + r) * 3;
                    out[o + 0] = nv[0];
                    out[o + 1] = nv[1];
                    out[o + 2] = nv[2];
                } else {
                    xout[b * S_ + r0 + r] = make_float4(nv[0], nv[1], nv[2], 0.f);
                }
            }
            if (t < NSTEPS_) __threadfence();   // release this warp's x writes
        }

        if (t < NSTEPS_) {
            __syncthreads();                     // all warps done with pos + writes issued
            if (tid == 0) {
                unsigned a = atomicAdd(&g_cnt[b], 1);
                if (a == 127u) {
                    atomicExch(&g_cnt[b], 0u);
                    __threadfence();
                    atomicAdd(&g_ph[b], 1u);
                } else {
                    const unsigned target = ph0 + (unsigned)t;
                    while (*(volatile unsigned*)&g_ph[b] < target) { __nanosleep(64); }
                }
                __threadfence();                 // acquire
            }
            __syncthreads();
        }
    }
}

// =====================================================================
// host launcher (graph-capturable: kernel launches only)
// =====================================================================
extern "C" void kernel_launch(void* const* d_in, const int* in_sizes, int n_in,
                              void* d_out, int out_size)
{
    const float* bf  = (const float*)d_in[0];   // backbone_features [4,1024,768]
    const float* cm  = (const float*)d_in[2];   // contact_map [4,1024,1024]
    const float* Wb1 = (const float*)d_in[3];
    const float* bb1 = (const float*)d_in[4];
    const float* Wb2 = (const float*)d_in[5];
    const float* bb2 = (const float*)d_in[6];
    float* out = (float*)d_out;

    gemm_relu_kernel<<<dim3(H_ / 64, NROW / 64), 256>>>(bf, Wb1, bb1);
    angles_delta_kernel<<<NROW, 128>>>(Wb2, bb2);
    cmsym_kernel<<<dim3(S_ / 32, S_ / 32, B_), dim3(32, 8)>>>(cm);
    cumsum_kernel<<<B_ * 3, S_>>>();
    refine_kernel<<<512, 128>>>(out);
}

// round 3
// speedup vs baseline: 1.7548x; 1.3420x over previous
#include <cuda_runtime.h>
#include <math.h>

#define B_  4
#define S_  1024
#define D_  768
#define H_  384
#define NROW (B_*S_)            // 4096
#define BOND_ 3.8f
#define LR_ 0.01f
#define BETA1_ 0.9f
#define BETA2_ 0.999f
#define ADAM_EPS_ 1e-8f
#define NSTEPS_ 50

typedef unsigned long long ull;

// ---------- packed f32x2 helpers (Blackwell FFMA2 path) ----------
__device__ __forceinline__ ull pk2(float lo, float hi) {
    ull r; asm("mov.b64 %0,{%1,%2};" : "=l"(r) : "f"(lo), "f"(hi)); return r;
}
__device__ __forceinline__ void upk2(ull v, float& lo, float& hi) {
    asm("mov.b64 {%0,%1},%2;" : "=f"(lo), "=f"(hi) : "l"(v));
}
__device__ __forceinline__ ull fma2(ull a, ull b, ull c) {
    ull r; asm("fma.rn.f32x2 %0,%1,%2,%3;" : "=l"(r) : "l"(a), "l"(b), "l"(c)); return r;
}
__device__ __forceinline__ ull add2(ull a, ull b) {
    ull r; asm("add.rn.f32x2 %0,%1,%2;" : "=l"(r) : "l"(a), "l"(b)); return r;
}
__device__ __forceinline__ ull mul2(ull a, ull b) {
    ull r; asm("mul.rn.f32x2 %0,%1,%2;" : "=l"(r) : "l"(a), "l"(b)); return r;
}

// ----- device scratch (no allocations allowed) -----
__device__ float g_h[NROW * H_];               // hidden after ReLU (6 MB)
__device__ float g_delta[NROW * 3];
__device__ float g_pA[3 * NROW];               // ping-pong positions, SoA planes x|y|z
__device__ float g_pB[3 * NROW];
__device__ float g_cms[(size_t)B_ * S_ * S_];  // symmetrized + prescaled contact map (16 MB)
__device__ unsigned g_cnt[B_];                 // per-batch barrier counters
__device__ unsigned g_ph[B_];                  // per-batch barrier phases (monotonic)

// =====================================================================
// K1a: g_h = ReLU(A[4096,768] @ W1[768,384] + b1)
// BM=BN=64, BK=16, 256 threads, 4x4 per thread, f32x2-packed FMAs
// =====================================================================
__global__ __launch_bounds__(256) void gemm_relu_kernel(
    const float* __restrict__ A, const float* __restrict__ W1,
    const float* __restrict__ b1)
{
    __shared__ float As[16][64];
    __shared__ float Bs[16][64];

    const int tid = threadIdx.x;
    const int tx = tid & 15;
    const int ty = tid >> 4;
    const int m0 = blockIdx.y * 64;
    const int n0 = blockIdx.x * 64;

    ull acc[4][2];
#pragma unroll
    for (int i = 0; i < 4; i++) { acc[i][0] = 0ull; acc[i][1] = 0ull; }

    for (int k0 = 0; k0 < D_; k0 += 16) {
        {
            int row = tid >> 2;
            int c4  = tid & 3;
            float4 a = *(const float4*)(A + (size_t)(m0 + row) * D_ + k0 + c4 * 4);
            As[c4 * 4 + 0][row] = a.x;
            As[c4 * 4 + 1][row] = a.y;
            As[c4 * 4 + 2][row] = a.z;
            As[c4 * 4 + 3][row] = a.w;
        }
        {
            int row = tid >> 4;
            int c4  = tid & 15;
            *(float4*)&Bs[row][c4 * 4] =
                *(const float4*)(W1 + (size_t)(k0 + row) * H_ + n0 + c4 * 4);
        }
        __syncthreads();

#pragma unroll
        for (int k = 0; k < 16; k++) {
            float a[4], bb[4];
            *(float4*)a  = *(const float4*)&As[k][ty * 4];
            *(float4*)bb = *(const float4*)&Bs[k][tx * 4];
            ull b01 = pk2(bb[0], bb[1]);
            ull b23 = pk2(bb[2], bb[3]);
#pragma unroll
            for (int i = 0; i < 4; i++) {
                ull ai = pk2(a[i], a[i]);
                acc[i][0] = fma2(ai, b01, acc[i][0]);
                acc[i][1] = fma2(ai, b23, acc[i][1]);
            }
        }
        __syncthreads();
    }

    float4 bias = *(const float4*)(b1 + n0 + tx * 4);
#pragma unroll
    for (int i = 0; i < 4; i++) {
        float v0, v1, v2, v3;
        upk2(acc[i][0], v0, v1);
        upk2(acc[i][1], v2, v3);
        float4 o;
        o.x = fmaxf(v0 + bias.x, 0.f);
        o.y = fmaxf(v1 + bias.y, 0.f);
        o.z = fmaxf(v2 + bias.z, 0.f);
        o.w = fmaxf(v3 + bias.w, 0.f);
        *(float4*)(g_h + (size_t)(m0 + ty * 4 + i) * H_ + n0 + tx * 4) = o;
    }
}

// =====================================================================
// K1b: per-row phi/psi = h @ W2[:,0:2] + b2, then delta vector
// =====================================================================
__global__ __launch_bounds__(128) void angles_delta_kernel(
    const float* __restrict__ W2, const float* __restrict__ b2)
{
    const int row = blockIdx.x;
    const int tid = threadIdx.x;
    const float* h = g_h + (size_t)row * H_;

    float a0 = 0.f, a1 = 0.f;
#pragma unroll
    for (int j = tid; j < H_; j += 128) {
        float hv = h[j];
        a0 = fmaf(hv, W2[j * 3 + 0], a0);
        a1 = fmaf(hv, W2[j * 3 + 1], a1);
    }
#pragma unroll
    for (int off = 16; off; off >>= 1) {
        a0 += __shfl_down_sync(0xffffffffu, a0, off);
        a1 += __shfl_down_sync(0xffffffffu, a1, off);
    }
    __shared__ float s0[4], s1[4];
    int w = tid >> 5, lane = tid & 31;
    if (lane == 0) { s0[w] = a0; s1[w] = a1; }
    __syncthreads();
    if (tid == 0) {
        float phi = s0[0] + s0[1] + s0[2] + s0[3] + b2[0];
        float psi = s1[0] + s1[1] + s1[2] + s1[3] + b2[1];
        float dx, dy, dz;
        if ((row & (S_ - 1)) == 0) {
            dx = dy = dz = 0.f;
        } else {
            float sp, cp, ss, cs;
            sincosf(phi, &sp, &cp);
            sincosf(psi, &ss, &cs);
            dx = BOND_ * cp * cs;
            dy = BOND_ * sp * cs;
            dz = BOND_ * ss;
        }
        g_delta[row * 3 + 0] = dx;
        g_delta[row * 3 + 1] = dy;
        g_delta[row * 3 + 2] = dz;
    }
}

// =====================================================================
// K2: inclusive cumsum per (batch, dim) -> g_pA SoA planes
// =====================================================================
__global__ __launch_bounds__(1024) void cumsum_kernel()
{
    const int b   = blockIdx.x / 3;
    const int dim = blockIdx.x % 3;
    const int s   = threadIdx.x;

    float v = g_delta[((b * S_) + s) * 3 + dim];
    int lane = s & 31, w = s >> 5;
#pragma unroll
    for (int off = 1; off < 32; off <<= 1) {
        float n = __shfl_up_sync(0xffffffffu, v, off);
        if (lane >= off) v += n;
    }
    __shared__ float wsum[32];
    if (lane == 31) wsum[w] = v;
    __syncthreads();
    if (w == 0) {
        float t = wsum[lane];
#pragma unroll
        for (int off = 1; off < 32; off <<= 1) {
            float n = __shfl_up_sync(0xffffffffu, t, off);
            if (lane >= off) t += n;
        }
        wsum[lane] = t;
    }
    __syncthreads();
    float excl = (w == 0) ? 0.f : wsum[w - 1];
    g_pA[dim * NROW + b * S_ + s] = v + excl;
}

// =====================================================================
// K0: cm_sym[b,i,j] = (cm[b,i,j] + cm[b,j,i]) / (B*S*S)
// =====================================================================
__global__ void cmsym_kernel(const float* __restrict__ cm)
{
    __shared__ float ts[32][33];
    const int b  = blockIdx.z;
    const int i0 = blockIdx.y * 32;
    const int j0 = blockIdx.x * 32;
    const float* cb = cm + (size_t)b * S_ * S_;
    float* ob = g_cms + (size_t)b * S_ * S_;
    const int tx = threadIdx.x, ty = threadIdx.y;
    const float invN = 1.0f / (float)((size_t)B_ * S_ * S_);

#pragma unroll
    for (int r = ty; r < 32; r += 8)
        ts[r][tx] = cb[(size_t)(j0 + r) * S_ + i0 + tx];
    __syncthreads();
#pragma unroll
    for (int r = ty; r < 32; r += 8)
        ob[(size_t)(i0 + r) * S_ + j0 + tx] =
            (cb[(size_t)(i0 + r) * S_ + j0 + tx] + ts[tx][r]) * invN;
}

// =====================================================================
// K3: persistent refine — 50 Adam steps, f32x2-packed inner loop.
// 128 blocks x 512 threads, 1 block/SM. Block owns 32 rows (2/warp).
// Dynamic smem: SoA positions (12KB) + 32 cm rows (128KB).
// =====================================================================
#define RTH 512
#define BPB 32      // blocks per batch
#define SMEM_REFINE ((3 * S_ + 32 * S_) * (int)sizeof(float))

extern __shared__ float smref[];

__global__ __launch_bounds__(RTH, 1) void refine_kernel(float* __restrict__ out)
{
    float* xs  = smref;
    float* ys  = xs + S_;
    float* zs  = ys + S_;
    float* cmr = zs + S_;     // [32][1024]

    const int tid  = threadIdx.x;
    const int w    = tid >> 5;
    const int lane = tid & 31;
    const int b    = blockIdx.x >> 5;          // /BPB
    const int rbse = (blockIdx.x & 31) * 32;   // row base within batch
    const int rA   = rbse + w * 2;             // warp's rows: rA, rA+1

    // cache this warp's 2 contact-map rows (once; reused 50 steps)
    {
        const float4* sA = (const float4*)(g_cms + ((size_t)b * S_ + rA) * S_);
        const float4* sB = (const float4*)(g_cms + ((size_t)b * S_ + rA + 1) * S_);
        float4* dA = (float4*)(cmr + (size_t)(w * 2) * S_);
        float4* dB = (float4*)(cmr + (size_t)(w * 2 + 1) * S_);
        for (int k = lane; k < S_ / 4; k += 32) { dA[k] = sA[k]; dB[k] = sB[k]; }
    }

    unsigned ph0 = 0;
    if (tid == 0) ph0 = *(volatile unsigned*)&g_ph[b];

    float m[2][3] = {{0,0,0},{0,0,0}};
    float v[2][3] = {{0,0,0},{0,0,0}};
    float b1t = 1.f, b2t = 1.f;

    const ull M1   = pk2(-1.f, -1.f);
    const ull EPS2 = pk2(1e-12f, 1e-12f);
    const ull N64  = pk2(-64.f, -64.f);
    const ull SGNM = 0x8000000080000000ull;

    const float* cApt = cmr + (size_t)(w * 2) * S_;
    const float* cBpt = cApt + S_;

    for (int t = 1; t <= NSTEPS_; t++) {
        const float* xin = (t & 1) ? g_pA : g_pB;
        float* xout      = (t & 1) ? g_pB : g_pA;

        // reload positions (L2-coherent)
        {
            const float4* px = (const float4*)(xin + 0 * NROW + b * S_);
            const float4* py = (const float4*)(xin + 1 * NROW + b * S_);
            const float4* pz = (const float4*)(xin + 2 * NROW + b * S_);
            for (int i = tid; i < S_ / 4; i += RTH) {
                ((float4*)xs)[i] = __ldcg(px + i);
                ((float4*)ys)[i] = __ldcg(py + i);
                ((float4*)zs)[i] = __ldcg(pz + i);
            }
        }
        __syncthreads();

        const float axA = xs[rA],     ayA = ys[rA],     azA = zs[rA];
        const float axB = xs[rA + 1], ayB = ys[rA + 1], azB = zs[rA + 1];
        const ull xiA = pk2(axA, axA), yiA = pk2(ayA, ayA), ziA = pk2(azA, azA);
        const ull xiB = pk2(axB, axB), yiB = pk2(ayB, ayB), ziB = pk2(azB, azB);

        ull gA0 = 0, gA1 = 0, gA2 = 0;
        ull gB0 = 0, gB1 = 0, gB2 = 0;

#pragma unroll 4
        for (int it = 0; it < 16; it++) {
            const int j = it * 64 + lane * 2;
            const ull xj  = *(const ull*)(xs + j);
            const ull yj  = *(const ull*)(ys + j);
            const ull zj  = *(const ull*)(zs + j);
            const ull cjA = *(const ull*)(cApt + j);
            const ull cjB = *(const ull*)(cBpt + j);
            // row A
            {
                ull dx = fma2(M1, xj, xiA);
                ull dy = fma2(M1, yj, yiA);
                ull dz = fma2(M1, zj, ziA);
                ull d2 = fma2(dx, dx, EPS2);
                d2 = fma2(dy, dy, d2);
                d2 = fma2(dz, dz, d2);
                ull sg = add2(d2, N64);
                ull cs = cjA ^ (sg & SGNM);
                float dl, dh; upk2(d2, dl, dh);
                ull inv = pk2(rsqrtf(dl), rsqrtf(dh));
                ull wg = mul2(cs, inv);
                gA0 = fma2(wg, dx, gA0);
                gA1 = fma2(wg, dy, gA1);
                gA2 = fma2(wg, dz, gA2);
            }
            // row B
            {
                ull dx = fma2(M1, xj, xiB);
                ull dy = fma2(M1, yj, yiB);
                ull dz = fma2(M1, zj, ziB);
                ull d2 = fma2(dx, dx, EPS2);
                d2 = fma2(dy, dy, d2);
                d2 = fma2(dz, dz, d2);
                ull sg = add2(d2, N64);
                ull cs = cjB ^ (sg & SGNM);
                float dl, dh; upk2(d2, dl, dh);
                ull inv = pk2(rsqrtf(dl), rsqrtf(dh));
                ull wg = mul2(cs, inv);
                gB0 = fma2(wg, dx, gB0);
                gB1 = fma2(wg, dy, gB1);
                gB2 = fma2(wg, dz, gB2);
            }
        }

        float gr[2][3];
        {
            float lo, hi;
            upk2(gA0, lo, hi); gr[0][0] = lo + hi;
            upk2(gA1, lo, hi); gr[0][1] = lo + hi;
            upk2(gA2, lo, hi); gr[0][2] = lo + hi;
            upk2(gB0, lo, hi); gr[1][0] = lo + hi;
            upk2(gB1, lo, hi); gr[1][1] = lo + hi;
            upk2(gB2, lo, hi); gr[1][2] = lo + hi;
        }
#pragma unroll
        for (int off = 16; off; off >>= 1) {
            gr[0][0] += __shfl_down_sync(0xffffffffu, gr[0][0], off);
            gr[0][1] += __shfl_down_sync(0xffffffffu, gr[0][1], off);
            gr[0][2] += __shfl_down_sync(0xffffffffu, gr[0][2], off);
            gr[1][0] += __shfl_down_sync(0xffffffffu, gr[1][0], off);
            gr[1][1] += __shfl_down_sync(0xffffffffu, gr[1][1], off);
            gr[1][2] += __shfl_down_sync(0xffffffffu, gr[1][2], off);
        }

        b1t *= BETA1_;
        b2t *= BETA2_;

        if (lane == 0) {
            const float c1f = 1.f / (1.f - b1t);
            const float c2f = 1.f / (1.f - b2t);
            float px[2][3] = {{axA, ayA, azA}, {axB, ayB, azB}};
#pragma unroll
            for (int r = 0; r < 2; r++) {
                float nv[3];
#pragma unroll
                for (int d = 0; d < 3; d++) {
                    m[r][d] = BETA1_ * m[r][d] + (1.f - BETA1_) * gr[r][d];
                    v[r][d] = BETA2_ * v[r][d] + (1.f - BETA2_) * gr[r][d] * gr[r][d];
                    nv[d] = px[r][d] - LR_ * (m[r][d] * c1f) / (sqrtf(v[r][d] * c2f) + ADAM_EPS_);
                }
                const int row = rA + r;
                if (t == NSTEPS_) {
                    size_t o = ((size_t)b * S_ + row) * 3;
                    out[o + 0] = nv[0];
                    out[o + 1] = nv[1];
                    out[o + 2] = nv[2];
                } else {
                    xout[0 * NROW + b * S_ + row] = nv[0];
                    xout[1 * NROW + b * S_ + row] = nv[1];
                    xout[2 * NROW + b * S_ + row] = nv[2];
                }
            }
            if (t < NSTEPS_) __threadfence();   // release this warp's x writes
        }

        if (t < NSTEPS_) {
            __syncthreads();
            if (tid == 0) {
                unsigned a = atomicAdd(&g_cnt[b], 1);
                if (a == (unsigned)(BPB - 1)) {
                    atomicExch(&g_cnt[b], 0u);
                    __threadfence();
                    atomicAdd(&g_ph[b], 1u);
                } else {
                    const unsigned target = ph0 + (unsigned)t;
                    while (*(volatile unsigned*)&g_ph[b] < target) { }
                }
                __threadfence();
            }
            __syncthreads();
        }
    }
}

// =====================================================================
// host launcher (graph-capturable: kernel launches only)
// =====================================================================
extern "C" void kernel_launch(void* const* d_in, const int* in_sizes, int n_in,
                              void* d_out, int out_size)
{
    const float* bf  = (const float*)d_in[0];
    const float* cm  = (const float*)d_in[2];
    const float* Wb1 = (const float*)d_in[3];
    const float* bb1 = (const float*)d_in[4];
    const float* Wb2 = (const float*)d_in[5];
    const float* bb2 = (const float*)d_in[6];
    float* out = (float*)d_out;

    static int smem_set = 0;
    if (!smem_set) {
        cudaFuncSetAttribute(refine_kernel,
                             cudaFuncAttributeMaxDynamicSharedMemorySize, SMEM_REFINE);
        smem_set = 1;
    }

    gemm_relu_kernel<<<dim3(H_ / 64, NROW / 64), 256>>>(bf, Wb1, bb1);
    angles_delta_kernel<<<NROW, 128>>>(Wb2, bb2);
    cmsym_kernel<<<dim3(S_ / 32, S_ / 32, B_), dim3(32, 8)>>>(cm);
    cumsum_kernel<<<B_ * 3, S_>>>();
    refine_kernel<<<128, RTH, SMEM_REFINE>>>(out);
}